// round 8
// baseline (speedup 1.0000x reference)
#include <cuda_runtime.h>
#include <cuda_fp16.h>
#include <cstdint>

// ============================================================
// Fused GRUCell, sm_103 base-PTX (ldmatrix + mma.sync.m16n8k16).
// Coalesced LDG.128 -> fp16 STS staging (per-warp, double-buffered)
// -> ldmatrix A-fragments. Next slab's loads issued in chunks ahead
// of gemm groups; pack/STS deferred behind them (latency hiding
// inside the warp). hx fragments reused for r*hx and the epilogue.
//   r = sig(x@Wir + hx@Whr + br); z = sig(x@Wiz + hx@Whz + bz)
//   n = tanh(x@Win + (r*hx)@Whn + bn); h = hx + z*(n - hx)
// B = 1048576, H = 64. M = 32 rows per warp per iteration.
// ============================================================

#define DEV __device__ __forceinline__

static constexpr int NSLAB = 1048576 / 32;       // 32768 slabs of 32 rows

// ---- dynamic SMEM layout (bytes) ----
static constexpr int OFF_W    = 0;               // 6 x [64x64] f16 SW128 rows = 49152
static constexpr int OFF_BIAS = 49152;           // 3 x 64 fp32 = 768
static constexpr int OFF_BUF  = 50176;           // per-warp staging
static constexpr int TILE_SZ  = 4096;            // 32 rows x 128B fp16
static constexpr int STAGE_SZ = 2 * TILE_SZ;     // x tile + hx tile
static constexpr int WARP_BUF = 2 * STAGE_SZ;    // double buffer
static constexpr int SMEM_SZ  = OFF_BUF + 8 * WARP_BUF;   // 181248

DEV uint32_t sw(uint32_t o) { return o ^ ((o >> 3) & 0x70); }

DEV uint32_t s2u(const void* p) {
    uint32_t a;
    asm("{ .reg .u64 t; cvta.to.shared.u64 t, %1; cvt.u32.u64 %0, t; }" : "=r"(a) : "l"(p));
    return a;
}

DEV void ldsm4(uint32_t& d0, uint32_t& d1, uint32_t& d2, uint32_t& d3, uint32_t a) {
    asm volatile("ldmatrix.sync.aligned.m8n8.x4.shared.b16 {%0,%1,%2,%3}, [%4];"
                 : "=r"(d0), "=r"(d1), "=r"(d2), "=r"(d3) : "r"(a));
}
DEV void ldsm4t(uint32_t& d0, uint32_t& d1, uint32_t& d2, uint32_t& d3, uint32_t a) {
    asm volatile("ldmatrix.sync.aligned.m8n8.x4.trans.shared.b16 {%0,%1,%2,%3}, [%4];"
                 : "=r"(d0), "=r"(d1), "=r"(d2), "=r"(d3) : "r"(a));
}

DEV void mma4(float* c, const uint32_t* a, uint32_t b0, uint32_t b1) {
    asm volatile(
        "mma.sync.aligned.m16n8k16.row.col.f32.f16.f16.f32 "
        "{%0,%1,%2,%3}, {%4,%5,%6,%7}, {%8,%9}, {%0,%1,%2,%3};"
        : "+f"(c[0]), "+f"(c[1]), "+f"(c[2]), "+f"(c[3])
        : "r"(a[0]), "r"(a[1]), "r"(a[2]), "r"(a[3]), "r"(b0), "r"(b1));
}

// single-MUFU activations
DEV float tanh_ap(float x) {
    float r;
    asm("tanh.approx.f32 %0, %1;" : "=f"(r) : "f"(x));
    return r;
}
DEV float sigm(float x) { return fmaf(0.5f, tanh_ap(0.5f * x), 0.5f); }

DEV uint32_t packh2(float a, float b) {
    __half2 h = __floats2half2_rn(a, b);
    return *(uint32_t*)&h;
}

// GEMM accumulate: acc[2][8][4] += A(32x64 reg frags) @ W(64x64 f16 smem)
DEV void gemm2(float acc[2][8][4], const uint32_t af[2][4][4], uint32_t wbase, int laneB) {
    #pragma unroll
    for (int kb = 0; kb < 4; kb++) {
        #pragma unroll
        for (int nbp = 0; nbp < 4; nbp++) {
            uint32_t b0, b1, b2, b3;
            ldsm4t(b0, b1, b2, b3, wbase + sw((uint32_t)(laneB + kb * 2048 + nbp * 32)));
            #pragma unroll
            for (int mb = 0; mb < 2; mb++) {
                mma4(acc[mb][2 * nbp],     af[mb][kb], b0, b1);
                mma4(acc[mb][2 * nbp + 1], af[mb][kb], b2, b3);
            }
        }
    }
}

// Build A-fragments for a 32x64 fp16 SW128 tile via ldmatrix.
DEV void build_af2(uint32_t af[2][4][4], uint32_t tile, int lane) {
    int rowA  = lane & 15;
    int colAB = (lane >> 4) * 16;
    #pragma unroll
    for (int mb = 0; mb < 2; mb++) {
        #pragma unroll
        for (int kb = 0; kb < 4; kb++) {
            uint32_t a = tile + sw((uint32_t)((mb * 16 + rowA) * 128 + kb * 32 + colAB));
            ldsm4(af[mb][kb][0], af[mb][kb][1], af[mb][kb][2], af[mb][kb][3], a);
        }
    }
}

// Chunked load/store: one chunk = 8 float4 = quarter of (x|hx) slab.
DEV void ldg_chunk(float4 v[8], const float4* base, int lane, int half) {
    #pragma unroll
    for (int u = 0; u < 8; u++) v[u] = base[lane + (half * 8 + u) * 32];
}
DEV void sts_chunk(const float4 v[8], char* buf, int lane, int half) {
    #pragma unroll
    for (int u = 0; u < 8; u++) {
        int idx = lane + (half * 8 + u) * 32;
        int row = idx >> 4, c4 = idx & 15;
        *(uint2*)(buf + sw((uint32_t)(row * 128 + c4 * 8))) =
            make_uint2(packh2(v[u].x, v[u].y), packh2(v[u].z, v[u].w));
    }
}

__global__ void __launch_bounds__(256, 1) gru_kernel(
    const float* __restrict__ x,    const float* __restrict__ hx,
    const float* __restrict__ w_ir, const float* __restrict__ w_hr,
    const float* __restrict__ w_iz, const float* __restrict__ w_hz,
    const float* __restrict__ w_in, const float* __restrict__ w_hn,
    const float* __restrict__ b_r,  const float* __restrict__ b_z,
    const float* __restrict__ b_n,  float* __restrict__ out)
{
    extern __shared__ char sm[];
    const uint32_t SB = s2u(sm);
    const int tid  = threadIdx.x;
    const int lane = tid & 31;
    const int wid  = tid >> 5;

    // ---- one-time: weights -> f16 SMEM ([k][n] rows of 128B, SW128), biases ----
    {
        const float* ws[6] = {w_ir, w_hr, w_iz, w_hz, w_in, w_hn};
        #pragma unroll 1
        for (int g = 0; g < 6; g++) {
            const float* w = ws[g];
            for (int i = tid; i < 4096; i += 256) {
                int k = i >> 6, n = i & 63;
                *(__half*)(sm + OFF_W + g * 8192 + sw((uint32_t)(k * 128 + n * 2))) =
                    __float2half_rn(w[i]);
            }
        }
        if (tid < 64) {
            float* bs = (float*)(sm + OFF_BIAS);
            bs[tid]       = b_r[tid];
            bs[64 + tid]  = b_z[tid];
            bs[128 + tid] = b_n[tid];
        }
    }
    __syncthreads();   // only CTA-wide barrier in the kernel

    const int laneB = (lane & 15) * 128 + ((lane >> 4) << 4);  // ldmatrix B lane offset
    const int q2    = (lane & 3) * 2;
    const int grow  = lane >> 2;

    char* wbuf = sm + OFF_BUF + wid * WARP_BUF;
    const long stride = 8L * gridDim.x;
    const long g0 = (long)blockIdx.x * 8 + wid;

    // ---- prologue: fill stage 0 with slab g0 ----
    {
        const float4* xs = ((const float4*)x)  + (size_t)g0 * 512;
        const float4* hs = ((const float4*)hx) + (size_t)g0 * 512;
        float4 t[8];
        #pragma unroll
        for (int half = 0; half < 2; half++) {
            ldg_chunk(t, xs, lane, half); sts_chunk(t, wbuf, lane, half);
            ldg_chunk(t, hs, lane, half); sts_chunk(t, wbuf + TILE_SZ, lane, half);
        }
    }

    int s = 0;
    for (long g = g0; g < NSLAB; g += stride, s ^= 1) {
        char* cbuf = wbuf + s * STAGE_SZ;
        char* nbuf = wbuf + (s ^ 1) * STAGE_SZ;
        const long gn  = g + stride;
        const bool more = gn < NSLAB;
        const float4* xn = ((const float4*)x)  + (size_t)(more ? gn : g) * 512;
        const float4* hn = ((const float4*)hx) + (size_t)(more ? gn : g) * 512;

        __syncwarp();

        // ---- A fragments from fp16 staging (current stage) ----
        uint32_t xf[2][4][4], hf[2][4][4];
        build_af2(xf, (uint32_t)(SB + (cbuf - sm)), lane);
        build_af2(hf, (uint32_t)(SB + (cbuf - sm) + TILE_SZ), lane);

        // ---- r = sig(x@Wir + hx@Whr + br) ----
        float rc[2][8][4];
        #pragma unroll
        for (int nb = 0; nb < 8; nb++) {
            float2 br = *(float2*)(sm + OFF_BIAS + (nb * 8 + q2) * 4);
            #pragma unroll
            for (int mb = 0; mb < 2; mb++) {
                rc[mb][nb][0] = br.x; rc[mb][nb][1] = br.y;
                rc[mb][nb][2] = br.x; rc[mb][nb][3] = br.y;
            }
        }
        float4 c0[8];
        if (more) ldg_chunk(c0, xn, lane, 0);          // issue ahead
        gemm2(rc, xf, SB + OFF_W, laneB);
        if (more) sts_chunk(c0, nbuf, lane, 0);
        float4 c1[8];
        if (more) ldg_chunk(c1, xn, lane, 1);
        gemm2(rc, hf, SB + OFF_W + 1 * 8192, laneB);
        if (more) sts_chunk(c1, nbuf, lane, 1);

        // ---- rh = sigmoid(rc) * hx (hf fragments, fp16) ----
        uint32_t rhf[2][4][4];
        #pragma unroll
        for (int mb = 0; mb < 2; mb++) {
            #pragma unroll
            for (int kb = 0; kb < 4; kb++) {
                const float* ce = rc[mb][2 * kb];
                const float* co = rc[mb][2 * kb + 1];
                __half2 s0 = __floats2half2_rn(sigm(ce[0]), sigm(ce[1]));
                __half2 s1 = __floats2half2_rn(sigm(ce[2]), sigm(ce[3]));
                __half2 s2 = __floats2half2_rn(sigm(co[0]), sigm(co[1]));
                __half2 s3 = __floats2half2_rn(sigm(co[2]), sigm(co[3]));
                __half2 m0 = __hmul2(s0, *(const __half2*)&hf[mb][kb][0]);
                __half2 m1 = __hmul2(s1, *(const __half2*)&hf[mb][kb][1]);
                __half2 m2 = __hmul2(s2, *(const __half2*)&hf[mb][kb][2]);
                __half2 m3 = __hmul2(s3, *(const __half2*)&hf[mb][kb][3]);
                rhf[mb][kb][0] = *(uint32_t*)&m0;
                rhf[mb][kb][1] = *(uint32_t*)&m1;
                rhf[mb][kb][2] = *(uint32_t*)&m2;
                rhf[mb][kb][3] = *(uint32_t*)&m3;
            }
        }

        // ---- n = x@Win + rh@Whn + bn ----
        float nc[2][8][4];
        #pragma unroll
        for (int nb = 0; nb < 8; nb++) {
            float2 bn = *(float2*)(sm + OFF_BIAS + 512 + (nb * 8 + q2) * 4);
            #pragma unroll
            for (int mb = 0; mb < 2; mb++) {
                nc[mb][nb][0] = bn.x; nc[mb][nb][1] = bn.y;
                nc[mb][nb][2] = bn.x; nc[mb][nb][3] = bn.y;
            }
        }
        float4 c2[8];
        if (more) ldg_chunk(c2, hn, lane, 0);
        gemm2(nc, xf, SB + OFF_W + 4 * 8192, laneB);
        if (more) sts_chunk(c2, nbuf + TILE_SZ, lane, 0);
        float4 c3[8];
        if (more) ldg_chunk(c3, hn, lane, 1);
        gemm2(nc, rhf, SB + OFF_W + 5 * 8192, laneB);
        if (more) sts_chunk(c3, nbuf + TILE_SZ, lane, 1);

        // ---- z = sig(x@Wiz + hx@Whz + bz) ----
        float zc[2][8][4];
        #pragma unroll
        for (int nb = 0; nb < 8; nb++) {
            float2 bz = *(float2*)(sm + OFF_BIAS + 256 + (nb * 8 + q2) * 4);
            #pragma unroll
            for (int mb = 0; mb < 2; mb++) {
                zc[mb][nb][0] = bz.x; zc[mb][nb][1] = bz.y;
                zc[mb][nb][2] = bz.x; zc[mb][nb][3] = bz.y;
            }
        }
        gemm2(zc, xf, SB + OFF_W + 2 * 8192, laneB);
        gemm2(zc, hf, SB + OFF_W + 3 * 8192, laneB);

        // ---- epilogue: h = hx + z*(n - hx); hx from hf fragments ----
        #pragma unroll
        for (int mb = 0; mb < 2; mb++) {
            const long rg = g * 32 + mb * 16 + grow;
            #pragma unroll
            for (int nb = 0; nb < 8; nb++) {
                int kb = nb >> 1, e = (nb & 1) * 2;
                float2 a = __half22float2(*(const __half2*)&hf[mb][kb][e]);     // row grow
                float2 b = __half22float2(*(const __half2*)&hf[mb][kb][e + 1]); // row grow+8
                const float* zz = zc[mb][nb];
                const float* nn = nc[mb][nb];
                float z0 = sigm(zz[0]), z1 = sigm(zz[1]);
                float z2 = sigm(zz[2]), z3 = sigm(zz[3]);
                float n0 = tanh_ap(nn[0]), n1 = tanh_ap(nn[1]);
                float n2 = tanh_ap(nn[2]), n3 = tanh_ap(nn[3]);
                *(float2*)(out + rg * 64 + (nb * 8 + q2)) =
                    make_float2(fmaf(z0, n0 - a.x, a.x), fmaf(z1, n1 - a.y, a.y));
                *(float2*)(out + (rg + 8) * 64 + (nb * 8 + q2)) =
                    make_float2(fmaf(z2, n2 - b.x, b.x), fmaf(z3, n3 - b.y, b.y));
            }
        }
    }
}

extern "C" void kernel_launch(void* const* d_in, const int* in_sizes, int n_in,
                              void* d_out, int out_size) {
    int sms = 0;
    cudaDeviceGetAttribute(&sms, cudaDevAttrMultiProcessorCount, 0);
    if (sms <= 0) sms = 148;
    cudaFuncSetAttribute(gru_kernel, cudaFuncAttributeMaxDynamicSharedMemorySize, SMEM_SZ);
    gru_kernel<<<sms, 256, SMEM_SZ>>>(
        (const float*)d_in[0], (const float*)d_in[1],
        (const float*)d_in[2], (const float*)d_in[3],
        (const float*)d_in[4], (const float*)d_in[5],
        (const float*)d_in[6], (const float*)d_in[7],
        (const float*)d_in[8], (const float*)d_in[9],
        (const float*)d_in[10], (float*)d_out);
}